// round 11
// baseline (speedup 1.0000x reference)
#include <cuda_runtime.h>
#include <cstdint>

#define BB 32
#define NN 65536
#define MM 64
#define TPB 256
#define BLOCKS_PER_IMG (NN / TPB)           // 256
#define EPSV 1e-6f

// Scratch (static __device__ globals: no runtime allocation)
__device__ unsigned long long g_gt_best[BB * MM];   // packed (iou_bits<<32)|(~pred_idx)
__device__ float4             g_partials[BB * BLOCKS_PER_IMG];
__device__ float4             g_img_raw[BB];        // raw sums (fls, vc, gts, pc)
__device__ float4             g_img[BB];            // per-image (cls, reg, npos, -)

// ---------------------------------------------------------------------------
__global__ void k_init() {
    int t = blockIdx.x * blockDim.x + threadIdx.x;
    if (t < BB * MM) g_gt_best[t] = 0ull;
}

// ---------------------------------------------------------------------------
__device__ __forceinline__ float warp_sum(float v) {
    #pragma unroll
    for (int o = 16; o > 0; o >>= 1) v += __shfl_down_sync(0xffffffffu, v, o);
    return v;
}

// Fused kernel: per-pred best-GT argmax + candidate-gated per-GT argmax
// (shared atomicMax, taken only when iou > 0.1) + focal/GIoU sums assuming
// no scatter (fixed up later for the <=64 scattered preds per image).
__global__ void __launch_bounds__(TPB) k_main(const float* __restrict__ pred,
                                              const float* __restrict__ gt) {
    const int b = blockIdx.x >> 8;                  // / BLOCKS_PER_IMG
    const int i = (blockIdx.x & 255) * TPB + threadIdx.x;

    __shared__ float4 sgt[MM];
    __shared__ float  sga[MM];
    __shared__ unsigned long long scand[MM];
    __shared__ float4 sredu[TPB / 32];

    if (threadIdx.x < MM) {
        float4 g4 = ((const float4*)gt)[(size_t)b * MM + threadIdx.x];
        sgt[threadIdx.x] = g4;
        sga[threadIdx.x] = (g4.z - g4.x) * (g4.w - g4.y);
        scand[threadIdx.x] = 0ull;
    }
    __syncthreads();

    const float* p = pred + ((size_t)b * NN + i) * 5;
    float cx = p[0], cy = p[1], w = p[2], h = p[3], obj = p[4];
    float px1 = cx - 0.5f * w, py1 = cy - 0.5f * h;
    float px2 = cx + 0.5f * w, py2 = cy + 0.5f * h;
    float area_p = (px2 - px1) * (py2 - py1);

    float bestv = 0.0f;     // iou >= 0 always; strict > keeps first max (j=0 if all zero)
    int   bestj = 0;
    const unsigned long long packed_i = (unsigned long long)(0xFFFFFFFFu - (unsigned int)i);

    #pragma unroll 8
    for (int j = 0; j < MM; j++) {
        float4 g = sgt[j];
        float ix1 = fmaxf(px1, g.x), iy1 = fmaxf(py1, g.y);
        float ix2 = fminf(px2, g.z), iy2 = fminf(py2, g.w);
        float inter = fmaxf(ix2 - ix1, 0.0f) * fmaxf(iy2 - iy1, 0.0f);
        float uni   = area_p + sga[j] - inter;
        float iou   = __fdividef(inter, fmaxf(uni, EPSV));
        if (iou > bestv) { bestv = iou; bestj = j; }
        if (iou > 0.1f) {   // rare (~1-2%): only these can win the scatter gate
            atomicMax(&scand[j],
                      ((unsigned long long)__float_as_uint(iou) << 32) | packed_i);
        }
    }

    // ---- loss assuming scat=false (fixed up later for scattered preds) ----
    bool pos0  = bestv > 0.5f;
    bool neg0  = bestv < 0.4f;
    bool valid = pos0 || neg0;

    float l   = obj;
    float t   = pos0 ? 1.0f : 0.0f;
    float bce = fmaxf(l, 0.0f) - l * t + log1pf(expf(-fabsf(l)));
    float pr  = 1.0f / (1.0f + expf(-l));
    float p_t = pos0 ? pr : 1.0f - pr;
    float a_t = pos0 ? 0.25f : 0.75f;
    float om  = 1.0f - p_t;
    float fl  = a_t * om * om * bce;

    float4 g = sgt[bestj];
    float x1 = fmaxf(px1, g.x), y1 = fmaxf(py1, g.y);
    float x2 = fminf(px2, g.z), y2 = fminf(py2, g.w);
    float inter = fmaxf(x2 - x1, 0.0f) * fmaxf(y2 - y1, 0.0f);
    float uni = area_p + sga[bestj] - inter;
    float iou = __fdividef(inter, fmaxf(uni, EPSV));
    float ex1 = fminf(px1, g.x), ey1 = fminf(py1, g.y);
    float ex2 = fmaxf(px2, g.z), ey2 = fmaxf(py2, g.w);
    float enc = (ex2 - ex1) * (ey2 - ey1);
    float giou = iou - __fdividef(enc - uni, fmaxf(enc, EPSV));
    float gterm = 1.0f - giou;

    float s0 = valid ? fl : 0.0f;
    float s1 = valid ? 1.0f : 0.0f;
    float s2 = pos0 ? gterm : 0.0f;
    float s3 = pos0 ? 1.0f : 0.0f;

    s0 = warp_sum(s0); s1 = warp_sum(s1); s2 = warp_sum(s2); s3 = warp_sum(s3);
    const int lane = threadIdx.x & 31, warp = threadIdx.x >> 5;
    if (lane == 0) sredu[warp] = make_float4(s0, s1, s2, s3);
    __syncthreads();

    // flush candidate table to global
    if (threadIdx.x < MM) {
        unsigned long long v = scand[threadIdx.x];
        if (v) atomicMax(&g_gt_best[b * MM + threadIdx.x], v);
    }
    if (threadIdx.x < (TPB / 32)) {
        float4 v = sredu[threadIdx.x];
        #pragma unroll
        for (int o = (TPB / 64); o > 0; o >>= 1) {
            v.x += __shfl_down_sync(0xffu, v.x, o);
            v.y += __shfl_down_sync(0xffu, v.y, o);
            v.z += __shfl_down_sync(0xffu, v.z, o);
            v.w += __shfl_down_sync(0xffu, v.w, o);
        }
        if (threadIdx.x == 0) g_partials[blockIdx.x] = v;
    }
}

// ---------------------------------------------------------------------------
// Per-image raw-sum reduction: one block per image, 256 partials each.
__global__ void __launch_bounds__(TPB) k_reduce_img() {
    const int b = blockIdx.x;
    __shared__ float4 s[TPB / 32];

    float4 v = g_partials[b * BLOCKS_PER_IMG + threadIdx.x];
    v.x = warp_sum(v.x); v.y = warp_sum(v.y);
    v.z = warp_sum(v.z); v.w = warp_sum(v.w);
    int lane = threadIdx.x & 31, warp = threadIdx.x >> 5;
    if (lane == 0) s[warp] = v;
    __syncthreads();
    if (threadIdx.x == 0) {
        float fls = 0.f, vc = 0.f, gts = 0.f, pc = 0.f;
        #pragma unroll
        for (int k = 0; k < TPB / 32; k++) {
            fls += s[k].x; vc += s[k].y; gts += s[k].z; pc += s[k].w;
        }
        g_img_raw[b] = make_float4(fls, vc, gts, pc);
    }
}

// ---------------------------------------------------------------------------
// Fixup: per image, visit the <=64 scattered preds (winners with iou > 0.1),
// dedup, and adjust the raw sums for preds whose pos flag flips to true.
__global__ void __launch_bounds__(MM) k_fixup(const float* __restrict__ pred,
                                              const float* __restrict__ gt) {
    const int b = blockIdx.x;
    const int j = threadIdx.x;

    __shared__ float4 sgt[MM];
    __shared__ float  sga[MM];
    __shared__ unsigned int sidx[MM];
    __shared__ float4 sredu[2];

    float4 g4 = ((const float4*)gt)[(size_t)b * MM + j];
    sgt[j] = g4;
    sga[j] = (g4.z - g4.x) * (g4.w - g4.y);

    unsigned long long pk = g_gt_best[b * MM + j];
    float val = __uint_as_float((unsigned int)(pk >> 32));
    unsigned int idx = 0xFFFFFFFFu - (unsigned int)(pk & 0xFFFFFFFFull);
    bool active = val > 0.1f;
    sidx[j] = active ? idx : 0xFFFFFFFFu;
    __syncthreads();

    // dedup: owner = lowest j holding this pred index
    bool owner = active;
    for (int jj = 0; jj < j; jj++) if (sidx[jj] == sidx[j]) { owner = false; break; }

    float d0 = 0.f, d1 = 0.f, d2 = 0.f, d3 = 0.f;
    if (owner) {
        const float* p = pred + ((size_t)b * NN + sidx[j]) * 5;
        float cx = p[0], cy = p[1], w = p[2], h = p[3], obj = p[4];
        float px1 = cx - 0.5f * w, py1 = cy - 0.5f * h;
        float px2 = cx + 0.5f * w, py2 = cy + 0.5f * h;
        float area_p = (px2 - px1) * (py2 - py1);

        // recompute bestv/bestj bit-identically to k_main
        float bestv = 0.0f; int bestj = 0;
        for (int jj = 0; jj < MM; jj++) {
            float4 g = sgt[jj];
            float ix1 = fmaxf(px1, g.x), iy1 = fmaxf(py1, g.y);
            float ix2 = fminf(px2, g.z), iy2 = fminf(py2, g.w);
            float inter = fmaxf(ix2 - ix1, 0.0f) * fmaxf(iy2 - iy1, 0.0f);
            float uni   = area_p + sga[jj] - inter;
            float iou   = __fdividef(inter, fmaxf(uni, EPSV));
            if (iou > bestv) { bestv = iou; bestj = jj; }
        }

        if (!(bestv > 0.5f)) {        // pos0 was false -> flips to pos
            bool valid0 = bestv < 0.4f;
            float l = obj;
            float lp = log1pf(expf(-fabsf(l)));
            float pr = 1.0f / (1.0f + expf(-l));
            // t=1 focal
            float bce1 = fmaxf(l, 0.0f) - l + lp;
            float om1  = 1.0f - pr;
            float fl1  = 0.25f * om1 * om1 * bce1;
            // t=0 focal (what was counted if valid0)
            float bce0 = fmaxf(l, 0.0f) + lp;
            float fl0  = 0.75f * pr * pr * bce0;

            // gterm vs gt[bestj]
            float4 g = sgt[bestj];
            float x1 = fmaxf(px1, g.x), y1 = fmaxf(py1, g.y);
            float x2 = fminf(px2, g.z), y2 = fminf(py2, g.w);
            float inter = fmaxf(x2 - x1, 0.0f) * fmaxf(y2 - y1, 0.0f);
            float uni = area_p + sga[bestj] - inter;
            float iou = __fdividef(inter, fmaxf(uni, EPSV));
            float ex1 = fminf(px1, g.x), ey1 = fminf(py1, g.y);
            float ex2 = fmaxf(px2, g.z), ey2 = fmaxf(py2, g.w);
            float enc = (ex2 - ex1) * (ey2 - ey1);
            float giou = iou - __fdividef(enc - uni, fmaxf(enc, EPSV));

            d0 = fl1 - (valid0 ? fl0 : 0.0f);
            d1 = valid0 ? 0.0f : 1.0f;
            d2 = 1.0f - giou;
            d3 = 1.0f;
        }
    }

    d0 = warp_sum(d0); d1 = warp_sum(d1); d2 = warp_sum(d2); d3 = warp_sum(d3);
    int lane = j & 31, warp = j >> 5;
    if (lane == 0) sredu[warp] = make_float4(d0, d1, d2, d3);
    __syncthreads();
    if (j == 0) {
        float4 a = sredu[0], c = sredu[1];
        float4 raw = g_img_raw[b];
        float fls = raw.x + a.x + c.x;
        float vc  = raw.y + a.y + c.y;
        float gts = raw.z + a.z + c.z;
        float pc  = raw.w + a.w + c.w;
        float cls = (vc > 0.0f) ? fls / fmaxf(vc, 1.0f) : 0.0f;
        float reg = (pc > 0.0f) ? gts / fmaxf(pc, 1.0f) : 0.0f;
        g_img[b] = make_float4(cls, reg, pc, 0.0f);
    }
}

// Final combine: one warp over 32 images.
__global__ void k_final2(float* __restrict__ out) {
    float4 v = g_img[threadIdx.x];
    float cls = warp_sum(v.x);
    float reg = warp_sum(v.y);
    float pc  = warp_sum(v.z);
    if (threadIdx.x == 0) {
        float num_pos = fmaxf(pc, 1.0f);
        out[0] = cls / (float)BB + 2.0f * (reg / num_pos * (float)BB);
    }
}

// ---------------------------------------------------------------------------
extern "C" void kernel_launch(void* const* d_in, const int* in_sizes, int n_in,
                              void* d_out, int out_size) {
    const float* pred = (const float*)d_in[0];
    const float* gt   = (const float*)d_in[1];
    if (n_in >= 2 && in_sizes[0] == BB * MM * 4 && in_sizes[1] == BB * NN * 5) {
        pred = (const float*)d_in[1];
        gt   = (const float*)d_in[0];
    }
    float* out = (float*)d_out;

    k_init<<<(BB * MM + 255) / 256, 256>>>();
    k_main<<<BB * BLOCKS_PER_IMG, TPB>>>(pred, gt);
    k_reduce_img<<<BB, TPB>>>();
    k_fixup<<<BB, MM>>>(pred, gt);
    k_final2<<<1, 32>>>(out);
}